// round 14
// baseline (speedup 1.0000x reference)
#include <cuda_runtime.h>
#include <cuda_bf16.h>
#include <cstdint>

// NoiseFilter, exact closed form (validated R3-R13, rel_err ~3e-7):
//   taps: ir0[j] = (1/128)(amp0 + 2*sum_{k=1..63} amp_k cos(pi*k*j/64) + amp64*(-1)^j)
//         h[j]   = ir0[j] * 0.5*(1+cos(pi*j/64)),  j = 0..63
//   s[t] = 2*u[t]-1,  Z[192..255]=0, Z[256+t]=s[t]
//   out[tau] = sum_d h[d]*Z[256+tau-d]  +  sum_d h[d]*Z[tau+d]   (2nd: tau>=192 only)
// R14: 8 outputs/thread, 8 pairs/block (R13 structure — halved L1), but the
// wrap-tail term runs in its OWN 16-iter mini-loop before the common causal
// loop. No program point holds both sliding windows live -> regs ~64 -> <=48,
// occupancy restored. Accs are shared across both loops (sum splits exactly).

#define PAIRS   8
#define THREADS 256
#define ZQ      82             // quads per pair: Zb floats [0,328) = Z[192,520)
#define PI64    0.04908738521234052f

#define SQ(x) ((x) ^ (((x) >> 3) & 1))   // quad-bank swizzle (stride-2-quad safe)

#define PACK2(dst, lo, hi) \
    asm("mov.b64 %0, {%1, %2};" : "=l"(dst) \
        : "r"(__float_as_uint(lo)), "r"(__float_as_uint(hi)))
#define FMA2(acc, a, b) \
    asm("fma.rn.f32x2 %0, %1, %2, %0;" : "+l"(acc) : "l"(a), "l"(b))
#define UNPACK2(lo, hi, v) \
    asm("mov.b64 {%0, %1}, %2;" : "=r"(lo), "=r"(hi) : "l"(v))

union UQ { float4 f; uint64_t u[2]; };   // u[0]=(x,y), u[1]=(z,w)

__global__ __launch_bounds__(THREADS, 5)
void noisefilter_kernel(const float* __restrict__ amp,    // [65536, 65]
                        const float* __restrict__ noise,  // [65536, 256]
                        float*       __restrict__ out)    // [65536, 256]
{
    __shared__ __align__(16) float4   Zb[PAIRS][ZQ];    // swizzled signal quads
    __shared__ __align__(16) uint64_t hd64[PAIRS][64];  // duplicated taps (h,h)
    __shared__ __align__(16) float    a_sh[PAIRS][68];  // 2*amp

    const int tid = threadIdx.x;
    const long long pairBase = (long long)blockIdx.x * PAIRS;

    // deposit / phase-B mapping: warp = pair
    const int dp = tid >> 5;          // pair for deposit & taps
    const int li = tid & 31;          // lane within pair-warp

    // ---- issue global noise loads early (2 quads per thread) ----
    const float4* n4 = (const float4*)noise;
    float4 v1 = n4[(pairBase + dp) * 64 + li];
    float4 v2 = n4[(pairBase + dp) * 64 + 32 + li];

    // ---- phase A: zero quads 0..15 (Z[192..256)); load amp (doubled) ----
    if (tid < 128) {
        int pp = tid >> 4, qz = tid & 15;
        Zb[pp][SQ(qz)] = make_float4(0.f, 0.f, 0.f, 0.f);
    }
    for (int i = tid; i < PAIRS * 65; i += THREADS) {
        int pp = i / 65, k = i - pp * 65;
        a_sh[pp][k] = 2.f * amp[(pairBase + pp) * 65 + k];
    }
    __syncthreads();

    // ---- phase B: deposit s = 2u-1 (quads 16..79); taps via sym-pair DCT ----
    {
        int q1 = 16 + li, q2 = 48 + li;
        Zb[dp][SQ(q1)] = make_float4(2.f*v1.x-1.f, 2.f*v1.y-1.f,
                                     2.f*v1.z-1.f, 2.f*v1.w-1.f);
        Zb[dp][SQ(q2)] = make_float4(2.f*v2.x-1.f, 2.f*v2.y-1.f,
                                     2.f*v2.z-1.f, 2.f*v2.w-1.f);
    }
    {
        const int jj = li;                               // 0..31
        const float4* a4 = (const float4*)a_sh[dp];
        const float a64  = a_sh[dp][64];

        float e, o;
        int m;
        {   // quad 0: k = 0 (DC), 1, 2, 3
            float4 g = a4[0];
            e = 0.5f * g.x + ((jj & 1) ? -0.5f : 0.5f) * a64;
            m = jj;
            o = g.y * __cosf((float)m * PI64);
            m = (m + jj) & 127;
            e = fmaf(g.z, __cosf((float)m * PI64), e);
            m = (m + jj) & 127;
            o = fmaf(g.w, __cosf((float)m * PI64), o);
        }
        #pragma unroll
        for (int i = 1; i < 16; i++) {                   // k = 4i .. 4i+3
            float4 g = a4[i];
            m = (m + jj) & 127; e = fmaf(g.x, __cosf((float)m * PI64), e);
            m = (m + jj) & 127; o = fmaf(g.y, __cosf((float)m * PI64), o);
            m = (m + jj) & 127; e = fmaf(g.z, __cosf((float)m * PI64), e);
            m = (m + jj) & 127; o = fmaf(g.w, __cosf((float)m * PI64), o);
        }
        float c1 = __cosf((float)jj * PI64);
        float hj = (e + o) * (1.f + c1) * (1.f / 256.f); // tap jj
        uint64_t d0; PACK2(d0, hj, hj);
        hd64[dp][jj] = d0;
        if (jj >= 1) {                                   // partner tap 64-jj
            float hp = (e - o) * (1.f - c1) * (1.f / 256.f);
            uint64_t d1; PACK2(d1, hp, hp);
            hd64[dp][64 - jj] = d1;
        } else {                                         // lane 0: tap 32
            float e32 = 0.5f * (a_sh[dp][0] + a64);
            #pragma unroll
            for (int k = 2; k <= 62; k += 2)
                e32 += ((k & 2) ? -1.f : 1.f) * a_sh[dp][k];
            float h32 = e32 * (1.f / 256.f);
            uint64_t d2; PACK2(d2, h32, h32);
            hd64[dp][32] = d2;
        }
    }
    __syncthreads();

    // ---- phase C: convolution, 8 outputs/thread ----
    // tid -> (p, r): r<24 (tail-free) fills warps 0..5; r>=24 warps 6..7.
    int p, r;
    if (tid < 192) { p = tid / 24;      r = tid % 24; }
    else           { int t = tid - 192; p = t >> 3;   r = 24 + (t & 7); }

    {
        const float4*     Zp = (const float4*)(Zb[p]);
        const ulonglong2* H2 = (const ulonglong2*)(hd64[p]);

        uint64_t o01 = 0ull, o23 = 0ull, o45 = 0ull, o67 = 0ull;

        // ---- tail mini-loop (warps 6-7 only): accs += sum h[d]*Z[tau+d] ----
        if (r >= 24) {
            UQ Vlo, Vmid, Vhi;
            Vlo.f  = Zp[SQ(2*r - 48)];
            Vmid.f = Zp[SQ(2*r - 47)];
            Vhi.f  = Zp[SQ(2*r - 46)];
            uint64_t V_l_yz, V_lw_mx, V_m_yz;
            PACK2(V_l_yz,  Vlo.f.y,  Vlo.f.z);
            PACK2(V_lw_mx, Vlo.f.w,  Vmid.f.x);
            PACK2(V_m_yz,  Vmid.f.y, Vmid.f.z);
            #pragma unroll
            for (int dq = 0; dq < 16; dq++) {
                const ulonglong2 Hp = H2[2*dq];      // (h0,h0),(h1,h1)
                const ulonglong2 Hq = H2[2*dq + 1];  // (h2,h2),(h3,h3)
                uint64_t V_mw_hx, V_h_yz;
                PACK2(V_mw_hx, Vmid.f.w, Vhi.f.x);
                PACK2(V_h_yz,  Vhi.f.y,  Vhi.f.z);
                // d=4dq:   V floats (0,1)(2,3)(4,5)(6,7)
                FMA2(o01, Hp.x, Vlo.u[0]);  FMA2(o23, Hp.x, Vlo.u[1]);
                FMA2(o45, Hp.x, Vmid.u[0]); FMA2(o67, Hp.x, Vmid.u[1]);
                // d=4dq+1: (1,2)(3,4)(5,6)(7,8)
                FMA2(o01, Hp.y, V_l_yz);    FMA2(o23, Hp.y, V_lw_mx);
                FMA2(o45, Hp.y, V_m_yz);    FMA2(o67, Hp.y, V_mw_hx);
                // d=4dq+2: (2,3)(4,5)(6,7)(8,9)
                FMA2(o01, Hq.x, Vlo.u[1]);  FMA2(o23, Hq.x, Vmid.u[0]);
                FMA2(o45, Hq.x, Vmid.u[1]); FMA2(o67, Hq.x, Vhi.u[0]);
                // d=4dq+3: (3,4)(5,6)(7,8)(9,10)
                FMA2(o01, Hq.y, V_lw_mx);   FMA2(o23, Hq.y, V_m_yz);
                FMA2(o45, Hq.y, V_mw_hx);   FMA2(o67, Hq.y, V_h_yz);
                // rotate V window + carried packs
                Vlo = Vmid; Vmid = Vhi;
                V_l_yz = V_m_yz; V_lw_mx = V_mw_hx; V_m_yz = V_h_yz;
                if (dq < 15) Vhi.f = Zp[SQ(2*r - 45 + dq)];
            }
        }

        // ---- common causal loop (all warps): accs += sum h[d]*Z[256+tau-d] ----
        {
            UQ Qmid, Qhi;
            Qmid.f = Zp[SQ(2*r + 16)];
            Qhi.f  = Zp[SQ(2*r + 17)];
            uint64_t P_m_yz, P_mw_hx, P_h_yz;
            PACK2(P_m_yz,  Qmid.f.y, Qmid.f.z);
            PACK2(P_mw_hx, Qmid.f.w, Qhi.f.x);
            PACK2(P_h_yz,  Qhi.f.y,  Qhi.f.z);
            #pragma unroll
            for (int dq = 0; dq < 16; dq++) {
                const ulonglong2 Hp = H2[2*dq];
                const ulonglong2 Hq = H2[2*dq + 1];
                UQ Qlo; Qlo.f = Zp[SQ(2*r + 15 - dq)];
                uint64_t P_l_yz, P_lw_mx;
                PACK2(P_l_yz,  Qlo.f.y, Qlo.f.z);
                PACK2(P_lw_mx, Qlo.f.w, Qmid.f.x);
                // d=4dq:   A floats f = 4,6,8,10 (rel Qlo)
                FMA2(o01, Hp.x, Qmid.u[0]); FMA2(o23, Hp.x, Qmid.u[1]);
                FMA2(o45, Hp.x, Qhi.u[0]);  FMA2(o67, Hp.x, Qhi.u[1]);
                // d=4dq+1: f = 3,5,7,9
                FMA2(o01, Hp.y, P_lw_mx);   FMA2(o23, Hp.y, P_m_yz);
                FMA2(o45, Hp.y, P_mw_hx);   FMA2(o67, Hp.y, P_h_yz);
                // d=4dq+2: f = 2,4,6,8
                FMA2(o01, Hq.x, Qlo.u[1]);  FMA2(o23, Hq.x, Qmid.u[0]);
                FMA2(o45, Hq.x, Qmid.u[1]); FMA2(o67, Hq.x, Qhi.u[0]);
                // d=4dq+3: f = 1,3,5,7
                FMA2(o01, Hq.y, P_l_yz);    FMA2(o23, Hq.y, P_lw_mx);
                FMA2(o45, Hq.y, P_m_yz);    FMA2(o67, Hq.y, P_mw_hx);
                // rotate window + carried packs
                Qhi = Qmid; Qmid = Qlo;
                P_h_yz = P_m_yz; P_mw_hx = P_lw_mx; P_m_yz = P_l_yz;
            }
        }

        uint32_t u0, u1, u2, u3, u4, u5, u6, u7;
        UNPACK2(u0, u1, o01); UNPACK2(u2, u3, o23);
        UNPACK2(u4, u5, o45); UNPACK2(u6, u7, o67);
        float4* o4 = (float4*)out + (pairBase + p) * 64 + 2*r;
        o4[0] = make_float4(__uint_as_float(u0), __uint_as_float(u1),
                            __uint_as_float(u2), __uint_as_float(u3));
        o4[1] = make_float4(__uint_as_float(u4), __uint_as_float(u5),
                            __uint_as_float(u6), __uint_as_float(u7));
    }
}

extern "C" void kernel_launch(void* const* d_in, const int* in_sizes, int n_in,
                              void* d_out, int out_size)
{
    const float* amp   = (const float*)d_in[0];   // filter_bank [16,4096,65]
    const float* noise = (const float*)d_in[1];   // noise_u     [16,4096,256]
    float* out = (float*)d_out;                   // [16, 4096*256, 1]

    const int total_pairs = in_sizes[0] / 65;     // 65536
    const int blocks = total_pairs / PAIRS;       // 8192
    noisefilter_kernel<<<blocks, THREADS>>>(amp, noise, out);
}

// round 15
// speedup vs baseline: 1.0331x; 1.0331x over previous
#include <cuda_runtime.h>
#include <cuda_bf16.h>
#include <cstdint>

// NoiseFilter, exact closed form (validated R3-R14, rel_err ~3e-7):
//   taps: ir0[j] = (1/128)(amp0 + 2*sum_{k=1..63} amp_k cos(pi*k*j/64) + amp64*(-1)^j)
//         h[j]   = ir0[j] * 0.5*(1+cos(pi*j/64)),  j = 0..63
//   s[t] = 2*u[t]-1,  Z[192..255]=0, Z[256+t]=s[t]
//   out[tau] = sum_d h[d]*Z[256+tau-d]  +  sum_d h[d]*Z[tau+d]   (2nd: tau>=192 only)
// R15: 8 outputs/thread, 8 pairs/block, split tail/causal loops (small live set),
// NO min-blocks clamp (R14's forced 48 regs spilled -> 5.4TB/s DRAM).
// Z stored parity-deinterleaved: Ze[i]=quad(2i), Zo[i]=quad(2i+1). The 8-output
// tiling makes every window load stride-1 per array -> conflict-free with ZERO
// swizzle/address alu; all loads are [base+imm]. Phase-B cosines use constant
// angles __cosf(k_const * phi): FMUL-imm + MUFU only (no IADD/AND/I2F chain).

#define PAIRS   8
#define THREADS 256
#define NE      40             // quads per parity array (covers quads 0..79)
#define PI64    0.04908738521234052f

#define PACK2(dst, lo, hi) \
    asm("mov.b64 %0, {%1, %2};" : "=l"(dst) \
        : "r"(__float_as_uint(lo)), "r"(__float_as_uint(hi)))
#define FMA2(acc, a, b) \
    asm("fma.rn.f32x2 %0, %1, %2, %0;" : "+l"(acc) : "l"(a), "l"(b))
#define UNPACK2(lo, hi, v) \
    asm("mov.b64 {%0, %1}, %2;" : "=r"(lo), "=r"(hi) : "l"(v))

union UQ { float4 f; uint64_t u[2]; };   // u[0]=(x,y), u[1]=(z,w)

__global__ __launch_bounds__(THREADS)
void noisefilter_kernel(const float* __restrict__ amp,    // [65536, 65]
                        const float* __restrict__ noise,  // [65536, 256]
                        float*       __restrict__ out)    // [65536, 256]
{
    // [p][0] = even quads (Ze), [p][1] = odd quads (Zo)
    __shared__ __align__(16) float4   Zeo[PAIRS][2][NE];
    __shared__ __align__(16) uint64_t hd64[PAIRS][64];  // duplicated taps (h,h)
    __shared__ __align__(16) float    a_sh[PAIRS][68];  // 2*amp

    const int tid = threadIdx.x;
    const long long pairBase = (long long)blockIdx.x * PAIRS;

    // deposit / phase-B mapping: warp = pair
    const int dp = tid >> 5;          // pair for deposit & taps
    const int li = tid & 31;          // lane within pair-warp

    // ---- issue global noise loads early (quads 2li, 2li+1) ----
    const float4* n4 = (const float4*)noise;
    float4 v1 = n4[(pairBase + dp) * 64 + 2 * li];
    float4 v2 = n4[(pairBase + dp) * 64 + 2 * li + 1];

    // ---- phase A: zero quads 0..15 (Ze[0..7], Zo[0..7]); load amp ----
    if (li < 8) {
        Zeo[dp][0][li] = make_float4(0.f, 0.f, 0.f, 0.f);
        Zeo[dp][1][li] = make_float4(0.f, 0.f, 0.f, 0.f);
    }
    for (int i = tid; i < PAIRS * 65; i += THREADS) {
        int pp = i / 65, k = i - pp * 65;
        a_sh[pp][k] = 2.f * amp[(pairBase + pp) * 65 + k];
    }
    __syncthreads();

    // ---- phase B: deposit s = 2u-1; taps via sym-pair DCT ----
    {
        // quad(16+2li) -> Ze[8+li], quad(17+2li) -> Zo[8+li]; stride-1 stores
        Zeo[dp][0][8 + li] = make_float4(2.f*v1.x-1.f, 2.f*v1.y-1.f,
                                         2.f*v1.z-1.f, 2.f*v1.w-1.f);
        Zeo[dp][1][8 + li] = make_float4(2.f*v2.x-1.f, 2.f*v2.y-1.f,
                                         2.f*v2.z-1.f, 2.f*v2.w-1.f);
    }
    {
        const int jj = li;                               // 0..31
        const float* a  = a_sh[dp];
        const float a64 = a[64];
        const float phi = (float)jj * PI64;              // theta = pi*jj/64

        // E = even-k sum (incl DC, Nyquist), O = odd-k sum; a[] holds 2*amp.
        float e = 0.5f * a[0] + ((jj & 1) ? -0.5f : 0.5f) * a64;
        float o = 0.f;
        #pragma unroll
        for (int k = 1; k < 64; k++) {
            float c = __cosf((float)k * phi);            // FMUL-imm + MUFU only
            if (k & 1) o = fmaf(a[k], c, o);
            else       e = fmaf(a[k], c, e);
        }
        float c1 = __cosf(phi);
        float hj = (e + o) * (1.f + c1) * (1.f / 256.f); // tap jj
        uint64_t d0; PACK2(d0, hj, hj);
        hd64[dp][jj] = d0;
        if (jj >= 1) {                                   // partner tap 64-jj
            float hp = (e - o) * (1.f - c1) * (1.f / 256.f);
            uint64_t d1; PACK2(d1, hp, hp);
            hd64[dp][64 - jj] = d1;
        } else {                                         // lane 0: tap 32
            float e32 = 0.5f * (a[0] + a64);
            #pragma unroll
            for (int k = 2; k <= 62; k += 2)
                e32 += ((k & 2) ? -1.f : 1.f) * a[k];
            float h32 = e32 * (1.f / 256.f);
            uint64_t d2; PACK2(d2, h32, h32);
            hd64[dp][32] = d2;
        }
    }
    __syncthreads();

    // ---- phase C: convolution, 8 outputs/thread ----
    // tid -> (p, r): r<24 (tail-free) fills warps 0..5; r>=24 warps 6..7.
    int p, r;
    if (tid < 192) { p = tid / 24;      r = tid % 24; }
    else           { int t = tid - 192; p = t >> 3;   r = 24 + (t & 7); }

    {
        const float4* pe = &Zeo[p][0][0] + r;   // Ze[r + imm]
        const float4* po = &Zeo[p][1][0] + r;   // Zo[r + imm]
        const ulonglong2* H2 = (const ulonglong2*)(hd64[p]);

        uint64_t o01 = 0ull, o23 = 0ull, o45 = 0ull, o67 = 0ull;

        // ---- tail mini-loop (warps 6-7): accs += sum h[d]*Z[tau+d] ----
        if (r >= 24) {
            UQ Vlo, Vmid, Vhi;                   // quads 2r-48, 2r-47, 2r-46
            Vlo.f  = pe[-24];
            Vmid.f = po[-24];
            Vhi.f  = pe[-23];
            uint64_t V_l_yz, V_lw_mx, V_m_yz;
            PACK2(V_l_yz,  Vlo.f.y,  Vlo.f.z);
            PACK2(V_lw_mx, Vlo.f.w,  Vmid.f.x);
            PACK2(V_m_yz,  Vmid.f.y, Vmid.f.z);
            #pragma unroll
            for (int dq = 0; dq < 16; dq++) {
                const ulonglong2 Hp = H2[2*dq];      // (h0,h0),(h1,h1)
                const ulonglong2 Hq = H2[2*dq + 1];  // (h2,h2),(h3,h3)
                uint64_t V_mw_hx, V_h_yz;
                PACK2(V_mw_hx, Vmid.f.w, Vhi.f.x);
                PACK2(V_h_yz,  Vhi.f.y,  Vhi.f.z);
                // d=4dq:   V floats (0,1)(2,3)(4,5)(6,7)
                FMA2(o01, Hp.x, Vlo.u[0]);  FMA2(o23, Hp.x, Vlo.u[1]);
                FMA2(o45, Hp.x, Vmid.u[0]); FMA2(o67, Hp.x, Vmid.u[1]);
                // d=4dq+1: (1,2)(3,4)(5,6)(7,8)
                FMA2(o01, Hp.y, V_l_yz);    FMA2(o23, Hp.y, V_lw_mx);
                FMA2(o45, Hp.y, V_m_yz);    FMA2(o67, Hp.y, V_mw_hx);
                // d=4dq+2: (2,3)(4,5)(6,7)(8,9)
                FMA2(o01, Hq.x, Vlo.u[1]);  FMA2(o23, Hq.x, Vmid.u[0]);
                FMA2(o45, Hq.x, Vmid.u[1]); FMA2(o67, Hq.x, Vhi.u[0]);
                // d=4dq+3: (3,4)(5,6)(7,8)(9,10)
                FMA2(o01, Hq.y, V_lw_mx);   FMA2(o23, Hq.y, V_m_yz);
                FMA2(o45, Hq.y, V_mw_hx);   FMA2(o67, Hq.y, V_h_yz);
                // rotate window + carried packs
                Vlo = Vmid; Vmid = Vhi;
                V_l_yz = V_m_yz; V_lw_mx = V_mw_hx; V_m_yz = V_h_yz;
                if (dq < 15) {
                    // fresh quad 2r-45+dq: dq even -> Zo[r-23+dq/2], odd -> Ze[r-22+(dq-1)/2]
                    Vhi.f = (dq & 1) ? pe[-22 + ((dq - 1) >> 1)]
                                     : po[-23 + (dq >> 1)];
                }
            }
        }

        // ---- common causal loop (all warps): accs += sum h[d]*Z[256+tau-d] ----
        {
            UQ Qmid, Qhi;                        // quads 2r+16, 2r+17
            Qmid.f = pe[8];
            Qhi.f  = po[8];
            uint64_t P_m_yz, P_mw_hx, P_h_yz;
            PACK2(P_m_yz,  Qmid.f.y, Qmid.f.z);
            PACK2(P_mw_hx, Qmid.f.w, Qhi.f.x);
            PACK2(P_h_yz,  Qhi.f.y,  Qhi.f.z);
            #pragma unroll
            for (int dq = 0; dq < 16; dq++) {
                const ulonglong2 Hp = H2[2*dq];
                const ulonglong2 Hq = H2[2*dq + 1];
                // quad 2r+15-dq: dq even -> Zo[r+7-dq/2], dq odd -> Ze[r+7-(dq>>1)]
                UQ Qlo;
                Qlo.f = (dq & 1) ? pe[7 - (dq >> 1)] : po[7 - (dq >> 1)];
                uint64_t P_l_yz, P_lw_mx;
                PACK2(P_l_yz,  Qlo.f.y, Qlo.f.z);
                PACK2(P_lw_mx, Qlo.f.w, Qmid.f.x);
                // d=4dq:   A floats f = 4,6,8,10 (rel Qlo)
                FMA2(o01, Hp.x, Qmid.u[0]); FMA2(o23, Hp.x, Qmid.u[1]);
                FMA2(o45, Hp.x, Qhi.u[0]);  FMA2(o67, Hp.x, Qhi.u[1]);
                // d=4dq+1: f = 3,5,7,9
                FMA2(o01, Hp.y, P_lw_mx);   FMA2(o23, Hp.y, P_m_yz);
                FMA2(o45, Hp.y, P_mw_hx);   FMA2(o67, Hp.y, P_h_yz);
                // d=4dq+2: f = 2,4,6,8
                FMA2(o01, Hq.x, Qlo.u[1]);  FMA2(o23, Hq.x, Qmid.u[0]);
                FMA2(o45, Hq.x, Qmid.u[1]); FMA2(o67, Hq.x, Qhi.u[0]);
                // d=4dq+3: f = 1,3,5,7
                FMA2(o01, Hq.y, P_l_yz);    FMA2(o23, Hq.y, P_lw_mx);
                FMA2(o45, Hq.y, P_m_yz);    FMA2(o67, Hq.y, P_mw_hx);
                // rotate window + carried packs
                Qhi = Qmid; Qmid = Qlo;
                P_h_yz = P_m_yz; P_mw_hx = P_lw_mx; P_m_yz = P_l_yz;
            }
        }

        uint32_t u0, u1, u2, u3, u4, u5, u6, u7;
        UNPACK2(u0, u1, o01); UNPACK2(u2, u3, o23);
        UNPACK2(u4, u5, o45); UNPACK2(u6, u7, o67);
        float4* o4 = (float4*)out + (pairBase + p) * 64 + 2*r;
        o4[0] = make_float4(__uint_as_float(u0), __uint_as_float(u1),
                            __uint_as_float(u2), __uint_as_float(u3));
        o4[1] = make_float4(__uint_as_float(u4), __uint_as_float(u5),
                            __uint_as_float(u6), __uint_as_float(u7));
    }
}

extern "C" void kernel_launch(void* const* d_in, const int* in_sizes, int n_in,
                              void* d_out, int out_size)
{
    const float* amp   = (const float*)d_in[0];   // filter_bank [16,4096,65]
    const float* noise = (const float*)d_in[1];   // noise_u     [16,4096,256]
    float* out = (float*)d_out;                   // [16, 4096*256, 1]

    const int total_pairs = in_sizes[0] / 65;     // 65536
    const int blocks = total_pairs / PAIRS;       // 8192
    noisefilter_kernel<<<blocks, THREADS>>>(amp, noise, out);
}